// round 15
// baseline (speedup 1.0000x reference)
#include <cuda_runtime.h>

#define NMAX  1536
#define TPB   256
#define EPT   6          // strided elements per thread (NMAX / TPB)
#define NWARP 8
#define NITER 20

__device__ int g_maxdeg;

// ---------------------------------------------------------------------------
// Kernel 1 (pre): per-group offset (redundant prefix sum) + degree count
// -> global max degree via atomicMax.
// ---------------------------------------------------------------------------
__global__ void __launch_bounds__(512)
pre_kernel(const int* __restrict__ sizes,
           const int* __restrict__ edges,
           int N, int B) {
    __shared__ int cnt[NMAX];
    __shared__ int red[16];
    __shared__ int s_off;

    int g = blockIdx.x;
    int t = threadIdx.x;
    int lane = t & 31, wid = t >> 5;

    int part = 0;
    for (int i = t; i < g; i += 512) part += sizes[i];
#pragma unroll
    for (int d = 16; d; d >>= 1) part += __shfl_xor_sync(0xffffffffu, part, d);
    if (lane == 0) red[wid] = part;
    __syncthreads();
    if (t == 0) {
        int s = 0;
#pragma unroll
        for (int w = 0; w < 16; ++w) s += red[w];
        s_off = s;
    }
    int n = sizes[g];
    __syncthreads();
    int off = s_off;

    for (int i = t; i < n; i += 512)
        cnt[i] = (i == 0 || i == n - 1) ? 1 : 2;
    __syncthreads();

    const int2* e2 = (const int2*)edges;
    int reBase = (N - B) + off;
    for (int i = t; i < n; i += 512) {
        int2 e = e2[reBase + i];
        atomicAdd(&cnt[e.x - off], 1);
        atomicAdd(&cnt[e.y - off], 1);
    }
    __syncthreads();

    int m = 0;
    for (int i = t; i < n; i += 512) m = max(m, cnt[i]);
#pragma unroll
    for (int d = 16; d; d >>= 1) m = max(m, __shfl_xor_sync(0xffffffffu, m, d));
    if (lane == 0) red[wid] = m;
    __syncthreads();
    if (t == 0) {
        int mm = red[0];
#pragma unroll
        for (int w = 1; w < 16; ++w) mm = max(mm, red[w]);
        atomicMax(&g_maxdeg, mm);
    }
}

// ---------------------------------------------------------------------------
// Kernel 2 (main): fused per-group solve. R8 AoS structure, lean hot loop:
// - combined single overflow test in Phase P (fast path: 2 plain STS)
// - unconditional ovf add in Phase R (no flag, no branch)
// ---------------------------------------------------------------------------
__global__ void __launch_bounds__(TPB, 3)
main_kernel(const float* __restrict__ x,
            const int*   __restrict__ sizes,
            const int*   __restrict__ edges,
            float*       __restrict__ out,
            int N, int B) {
    __shared__ float ys[NMAX];
    __shared__ float uc[NMAX];
    __shared__ float ev[4 * NMAX];     // AoS: 4 contribution slots per node
    __shared__ float ovf[NMAX];        // overflow accum; int-aliased as cnt during setup
    __shared__ float red_s[NWARP];
    __shared__ int   red_c[NWARP];
    __shared__ int   red_i[NWARP];
    __shared__ float s_tau;
    __shared__ int   s_cnt;
    __shared__ int   s_off;

    int g = blockIdx.x;
    int t = threadIdx.x;
    int lane = t & 31, wid = t >> 5;

    // offset[g] = sum of sizes[0..g)  (redundant recompute; L2-resident)
    {
        int part = 0;
        for (int i = t; i < g; i += TPB) part += sizes[i];
#pragma unroll
        for (int d = 16; d; d >>= 1) part += __shfl_xor_sync(0xffffffffu, part, d);
        if (lane == 0) red_i[wid] = part;
        __syncthreads();
        if (t == 0) {
            int s = 0;
#pragma unroll
            for (int w = 0; w < NWARP; ++w) s += red_i[w];
            s_off = s;
        }
    }
    int n = sizes[g];
    __syncthreads();
    int off = s_off;
    int reBase = (N - B) + off;

    float xr[EPT], ur[EPT], ucv[EPT], yv[EPT];
    int   ea[EPT], eb[EPT];
    unsigned slp[EPT];     // packed slot addrs: sa | (sb<<16); 0xFFFF = overflow

    int* cnt = (int*)ovf;

    const int2* e2 = (const int2*)edges;
#pragma unroll
    for (int j = 0; j < EPT; ++j) {
        int i = t + j * TPB;
        bool a = (j < 2) || (i < n);   // first 512 slots always active (n>=512)
        if (a) {
            xr[j] = x[off + i];
            int2 e = e2[reBase + i];
            ea[j] = e.x - off;
            eb[j] = e.y - off;
            ys[i] = xr[j];
        } else {
            xr[j] = 0.0f; ea[j] = 0; eb[j] = 0;
            ys[i] = 0.0f;
        }
        uc[i] = 0.0f; cnt[i] = 0;
        yv[j]  = xr[j];
        ur[j]  = 0.0f;
        ucv[j] = 0.0f;
    }
#pragma unroll
    for (int k = 0; k < 4 * EPT; ++k)
        ev[t + k * TPB] = 0.0f;
    float step = 0.5f / (float)g_maxdeg;
    __syncthreads();

    // claim per-endpoint slots; precompute packed AoS store addresses
#pragma unroll
    for (int j = 0; j < EPT; ++j) {
        int i = t + j * TPB;
        bool a = (j < 2) || (i < n);
        if (a) {
            int pa = atomicAdd(&cnt[ea[j]], 1);
            int pb = atomicAdd(&cnt[eb[j]], 1);
            unsigned sa = (pa < 4) ? (unsigned)(4 * ea[j] + pa) : 0xFFFFu;
            unsigned sb = (pb < 4) ? (unsigned)(4 * eb[j] + pb) : 0xFFFFu;
            slp[j] = sa | (sb << 16);
        } else slp[j] = 0xFFFFu | (0xFFFFu << 16);
    }
    __syncthreads();
    // re-init ovf as float zero (always summed in Phase R; stays 0 for
    // nodes without overflow)
#pragma unroll
    for (int j = 0; j < EPT; ++j) {
        int i = t + j * TPB;
        ovf[i] = 0.0f;
    }
    __syncthreads();

    // ---- 20 iterations, 2 barriers each ----
    for (int it = 0; it < NITER; ++it) {
        // Phase P: dual updates from current y; publish contributions.
#pragma unroll
        for (int j = 0; j < EPT; ++j) {
            int i = t + j * TPB;
            bool a = (j < 2) || (i < n);
            if (a) {
                if (i < n - 1) {
                    float nu = ucv[j] + step * (yv[j] - ys[i + 1]);
                    nu = fminf(1.0f, fmaxf(-1.0f, nu));
                    ucv[j] = nu;
                    uc[i] = nu;
                }
                float ya = ys[ea[j]], yb = ys[eb[j]];
                float nu = ur[j] + step * (ya - yb);
                nu = fminf(1.0f, fmaxf(-1.0f, nu));
                unsigned s = slp[j];
                if ((s & 0x80008000u) == 0u) {
                    // fast path (both slots valid): two plain stores
                    ev[s & 0xFFFFu] = -nu;
                    ev[s >> 16]     =  nu;
                } else {
                    unsigned sa = s & 0xFFFFu;
                    unsigned sb = s >> 16;
                    if (sa != 0xFFFFu) ev[sa] = -nu;
                    else               atomicAdd(&ovf[ea[j]], -(nu - ur[j]));
                    if (sb != 0xFFFFu) ev[sb] =  nu;
                    else               atomicAdd(&ovf[eb[j]],  (nu - ur[j]));
                }
                ur[j] = nu;
            }
        }
        __syncthreads();
        // Phase R: rebuild y = x + uc[i-1] - uc[i] + sum(slots) + ovf.
#pragma unroll
        for (int j = 0; j < EPT; ++j) {
            int i = t + j * TPB;
            bool a = (j < 2) || (i < n);
            if (a) {
                float4 e4 = *(const float4*)&ev[4 * i];
                float v = xr[j] + ((e4.x + e4.y) + (e4.z + e4.w)) + ovf[i];
                if (i > 0)     v += uc[i - 1];
                if (i < n - 1) v -= ucv[j];
                yv[j] = v;
                ys[i] = v;
            }
        }
        __syncthreads();
    }

    // ---- sparsemax via Michelot (exact, no sort) ----
    {
        float s = 0.0f;
#pragma unroll
        for (int j = 0; j < EPT; ++j) {
            int i = t + j * TPB;
            if ((j < 2) || (i < n)) s += yv[j];
        }
#pragma unroll
        for (int d = 16; d; d >>= 1) s += __shfl_xor_sync(0xffffffffu, s, d);
        if (lane == 0) red_s[wid] = s;
        __syncthreads();
        if (t == 0) {
            float ss = 0.0f;
#pragma unroll
            for (int w = 0; w < NWARP; ++w) ss += red_s[w];
            s_tau = (ss - 1.0f) / (float)n;
            s_cnt = n;
        }
        __syncthreads();
    }

    float tau = s_tau;
    int prev_cnt = s_cnt;

    for (int itm = 0; itm < 64; ++itm) {
        float s = 0.0f;
        int   c = 0;
#pragma unroll
        for (int j = 0; j < EPT; ++j) {
            int i = t + j * TPB;
            bool a = (j < 2) || (i < n);
            if (a && yv[j] > tau) { s += yv[j]; ++c; }
        }
#pragma unroll
        for (int d = 16; d; d >>= 1) {
            s += __shfl_xor_sync(0xffffffffu, s, d);
            c += __shfl_xor_sync(0xffffffffu, c, d);
        }
        if (lane == 0) { red_s[wid] = s; red_c[wid] = c; }
        __syncthreads();
        if (t == 0) {
            float ss = 0.0f; int cc = 0;
#pragma unroll
            for (int w = 0; w < NWARP; ++w) { ss += red_s[w]; cc += red_c[w]; }
            s_tau = (ss - 1.0f) / (float)cc;
            s_cnt = cc;
        }
        __syncthreads();
        tau = s_tau;
        int cnt_now = s_cnt;
        if (cnt_now == prev_cnt) break;
        prev_cnt = cnt_now;
    }

    float scale = (float)n;
#pragma unroll
    for (int j = 0; j < EPT; ++j) {
        int i = t + j * TPB;
        if ((j < 2) || (i < n))
            out[off + i] = fmaxf(yv[j] - tau, 0.0f) * scale;
    }
}

// ---------------------------------------------------------------------------
extern "C" void kernel_launch(void* const* d_in, const int* in_sizes, int n_in,
                              void* d_out, int out_size) {
    const float* x     = (const float*)d_in[0];
    const int*   sizes = (const int*)  d_in[1];
    const int*   edges = (const int*)  d_in[2];
    float*       out   = (float*)d_out;
    int N = in_sizes[0];
    int B = in_sizes[1];

    pre_kernel<<<B, 512>>>(sizes, edges, N, B);
    main_kernel<<<B, TPB>>>(x, sizes, edges, out, N, B);
}

// round 16
// speedup vs baseline: 1.0532x; 1.0532x over previous
#include <cuda_runtime.h>

#define NMAX  1536
#define TPB   256
#define NP    3          // pairs per thread (NMAX / 2 / TPB)
#define NWARP 8
#define NITER 20

__device__ int g_maxdeg;

// ---------------------------------------------------------------------------
// Kernel 1 (pre): per-group offset (redundant prefix sum) + degree count
// -> global max degree via atomicMax.
// ---------------------------------------------------------------------------
__global__ void __launch_bounds__(512)
pre_kernel(const int* __restrict__ sizes,
           const int* __restrict__ edges,
           int N, int B) {
    __shared__ int cnt[NMAX];
    __shared__ int red[16];
    __shared__ int s_off;

    int g = blockIdx.x;
    int t = threadIdx.x;
    int lane = t & 31, wid = t >> 5;

    int part = 0;
    for (int i = t; i < g; i += 512) part += sizes[i];
#pragma unroll
    for (int d = 16; d; d >>= 1) part += __shfl_xor_sync(0xffffffffu, part, d);
    if (lane == 0) red[wid] = part;
    __syncthreads();
    if (t == 0) {
        int s = 0;
#pragma unroll
        for (int w = 0; w < 16; ++w) s += red[w];
        s_off = s;
    }
    int n = sizes[g];
    __syncthreads();
    int off = s_off;

    for (int i = t; i < n; i += 512)
        cnt[i] = (i == 0 || i == n - 1) ? 1 : 2;
    __syncthreads();

    const int2* e2 = (const int2*)edges;
    int reBase = (N - B) + off;
    for (int i = t; i < n; i += 512) {
        int2 e = e2[reBase + i];
        atomicAdd(&cnt[e.x - off], 1);
        atomicAdd(&cnt[e.y - off], 1);
    }
    __syncthreads();

    int m = 0;
    for (int i = t; i < n; i += 512) m = max(m, cnt[i]);
#pragma unroll
    for (int d = 16; d; d >>= 1) m = max(m, __shfl_xor_sync(0xffffffffu, m, d));
    if (lane == 0) red[wid] = m;
    __syncthreads();
    if (t == 0) {
        int mm = red[0];
#pragma unroll
        for (int w = 1; w < 16; ++w) mm = max(mm, red[w]);
        atomicMax(&g_maxdeg, mm);
    }
}

// ---------------------------------------------------------------------------
// Kernel 2 (main): fused per-group solve. R8 structure with contiguous-pair
// ownership: float2 ys/uc traffic, in-register chain neighbors.
// ---------------------------------------------------------------------------
__global__ void __launch_bounds__(TPB, 3)
main_kernel(const float* __restrict__ x,
            const int*   __restrict__ sizes,
            const int*   __restrict__ edges,
            float*       __restrict__ out,
            int N, int B) {
    __shared__ float2 ys2[NMAX / 2];
    __shared__ float2 uc2[NMAX / 2];
    __shared__ float  ev[4 * NMAX];      // AoS: 4 contribution slots per node
    __shared__ float2 ovf2[NMAX / 2];    // overflow accum; int-aliased as cnt during setup
    __shared__ float red_s[NWARP];
    __shared__ int   red_c[NWARP];
    __shared__ int   red_i[NWARP];
    __shared__ float s_tau;
    __shared__ int   s_cnt;
    __shared__ int   s_off;

    float* ysf  = (float*)ys2;
    float* ucf  = (float*)uc2;
    float* ovff = (float*)ovf2;
    int*   cnt  = (int*)ovf2;

    int g = blockIdx.x;
    int t = threadIdx.x;
    int lane = t & 31, wid = t >> 5;

    // offset[g] = sum of sizes[0..g)  (redundant recompute; L2-resident)
    {
        int part = 0;
        for (int i = t; i < g; i += TPB) part += sizes[i];
#pragma unroll
        for (int d = 16; d; d >>= 1) part += __shfl_xor_sync(0xffffffffu, part, d);
        if (lane == 0) red_i[wid] = part;
        __syncthreads();
        if (t == 0) {
            int s = 0;
#pragma unroll
            for (int w = 0; w < NWARP; ++w) s += red_i[w];
            s_off = s;
        }
    }
    int n = sizes[g];
    __syncthreads();
    int off = s_off;
    int reBase = (N - B) + off;

    // per-pair state: element i0 = 2p, i1 = 2p+1 with p = t + j*TPB
    float x0[NP], x1[NP], y0[NP], y1[NP];
    float u0[NP], u1[NP];              // chain duals for edges (i0,i0+1), (i1,i1+1)
    float r0[NP], r1[NP];              // random-edge duals owned by i0, i1
    int   ea0[NP], eb0[NP], ea1[NP], eb1[NP];
    unsigned sl0[NP], sl1[NP];
    unsigned ovfm = 0;                 // bit 2j: i0 overflow, bit 2j+1: i1

    const int2* e2 = (const int2*)edges;
#pragma unroll
    for (int j = 0; j < NP; ++j) {
        int p  = t + j * TPB;
        int i0 = 2 * p;
        bool a0 = (j == 0) || (i0 < n);        // j==0 -> i0<=510 < 512 <= n
        bool a1 = (j == 0) || (i0 + 1 < n);
        float v0 = 0.0f, v1 = 0.0f;
        if (a0) {
            v0 = x[off + i0];
            int2 e = e2[reBase + i0];
            ea0[j] = e.x - off;  eb0[j] = e.y - off;
        } else { ea0[j] = 0; eb0[j] = 0; }
        if (a1) {
            v1 = x[off + i0 + 1];
            int2 e = e2[reBase + i0 + 1];
            ea1[j] = e.x - off;  eb1[j] = e.y - off;
        } else { ea1[j] = 0; eb1[j] = 0; }
        x0[j] = v0; x1[j] = v1;
        y0[j] = v0; y1[j] = v1;
        ys2[p] = make_float2(v0, v1);
        uc2[p] = make_float2(0.0f, 0.0f);
        cnt[i0] = 0; cnt[i0 + 1] = 0;
        u0[j] = 0.0f; u1[j] = 0.0f;
        r0[j] = 0.0f; r1[j] = 0.0f;
    }
#pragma unroll
    for (int k = 0; k < 4 * 2 * NP; ++k)
        ev[t + k * TPB] = 0.0f;
    float step = 0.5f / (float)g_maxdeg;
    __syncthreads();

    // claim per-endpoint slots; precompute packed AoS store addresses
#pragma unroll
    for (int j = 0; j < NP; ++j) {
        int p  = t + j * TPB;
        int i0 = 2 * p;
        bool a0 = (j == 0) || (i0 < n);
        bool a1 = (j == 0) || (i0 + 1 < n);
        if (a0) {
            int pa = atomicAdd(&cnt[ea0[j]], 1);
            int pb = atomicAdd(&cnt[eb0[j]], 1);
            unsigned sa = (pa < 4) ? (unsigned)(4 * ea0[j] + pa) : 0xFFFFu;
            unsigned sb = (pb < 4) ? (unsigned)(4 * eb0[j] + pb) : 0xFFFFu;
            sl0[j] = sa | (sb << 16);
        } else sl0[j] = 0xFFFFu | (0xFFFFu << 16);
        if (a1) {
            int pa = atomicAdd(&cnt[ea1[j]], 1);
            int pb = atomicAdd(&cnt[eb1[j]], 1);
            unsigned sa = (pa < 4) ? (unsigned)(4 * ea1[j] + pa) : 0xFFFFu;
            unsigned sb = (pb < 4) ? (unsigned)(4 * eb1[j] + pb) : 0xFFFFu;
            sl1[j] = sa | (sb << 16);
        } else sl1[j] = 0xFFFFu | (0xFFFFu << 16);
    }
    __syncthreads();
    // read overflow flags (deg>4), then re-init ovf as float zero
#pragma unroll
    for (int j = 0; j < NP; ++j) {
        int i0 = 2 * (t + j * TPB);
        if (cnt[i0]     > 4) ovfm |= (1u << (2 * j));
        if (cnt[i0 + 1] > 4) ovfm |= (1u << (2 * j + 1));
    }
    __syncthreads();
#pragma unroll
    for (int j = 0; j < NP; ++j)
        ovf2[t + j * TPB] = make_float2(0.0f, 0.0f);
    __syncthreads();

    // ---- 20 iterations, 2 barriers each ----
    for (int it = 0; it < NITER; ++it) {
        // Phase P: dual updates from current y; publish contributions.
#pragma unroll
        for (int j = 0; j < NP; ++j) {
            int p  = t + j * TPB;
            int i0 = 2 * p;
            bool a0 = (j == 0) || (i0 < n);
            bool a1 = (j == 0) || (i0 + 1 < n);
            if (a0) {
                // chain dual (i0 -> i0+1): neighbor y in register
                if (i0 < n - 1) {
                    float nu = u0[j] + step * (y0[j] - y1[j]);
                    u0[j] = fminf(1.0f, fmaxf(-1.0f, nu));
                }
                // chain dual (i0+1 -> i0+2): one LDS
                if (i0 + 1 < n - 1) {
                    float yn = ysf[i0 + 2];
                    float nu = u1[j] + step * (y1[j] - yn);
                    u1[j] = fminf(1.0f, fmaxf(-1.0f, nu));
                }
                uc2[p] = make_float2(u0[j], u1[j]);   // single STS.64
                // random edge of i0
                {
                    float nu = r0[j] + step * (ysf[ea0[j]] - ysf[eb0[j]]);
                    nu = fminf(1.0f, fmaxf(-1.0f, nu));
                    unsigned sa = sl0[j] & 0xFFFFu;
                    unsigned sb = sl0[j] >> 16;
                    if (sa != 0xFFFFu) ev[sa] = -nu;
                    else               atomicAdd(&ovff[ea0[j]], -(nu - r0[j]));
                    if (sb != 0xFFFFu) ev[sb] =  nu;
                    else               atomicAdd(&ovff[eb0[j]],  (nu - r0[j]));
                    r0[j] = nu;
                }
                // random edge of i0+1
                if (a1) {
                    float nu = r1[j] + step * (ysf[ea1[j]] - ysf[eb1[j]]);
                    nu = fminf(1.0f, fmaxf(-1.0f, nu));
                    unsigned sa = sl1[j] & 0xFFFFu;
                    unsigned sb = sl1[j] >> 16;
                    if (sa != 0xFFFFu) ev[sa] = -nu;
                    else               atomicAdd(&ovff[ea1[j]], -(nu - r1[j]));
                    if (sb != 0xFFFFu) ev[sb] =  nu;
                    else               atomicAdd(&ovff[eb1[j]],  (nu - r1[j]));
                    r1[j] = nu;
                }
            }
        }
        __syncthreads();
        // Phase R: rebuild y = x + uc[i-1] - uc[i] + sum(slots) [+ ovf]
#pragma unroll
        for (int j = 0; j < NP; ++j) {
            int p  = t + j * TPB;
            int i0 = 2 * p;
            bool a0 = (j == 0) || (i0 < n);
            bool a1 = (j == 0) || (i0 + 1 < n);
            if (a0) {
                float4 e4a = *(const float4*)&ev[4 * i0];
                float4 e4b = *(const float4*)&ev[4 * i0 + 4];
                float v0 = x0[j] + ((e4a.x + e4a.y) + (e4a.z + e4a.w));
                float v1 = x1[j] + ((e4b.x + e4b.y) + (e4b.z + e4b.w));
                if (ovfm & (1u << (2 * j)))     v0 += ovff[i0];
                if (ovfm & (1u << (2 * j + 1))) v1 += ovff[i0 + 1];
                if (i0 > 0) v0 += ucf[i0 - 1];         // one LDS per pair
                if (i0 < n - 1) { v0 -= u0[j]; v1 += u0[j]; }  // in-register
                if (i0 + 1 < n - 1) v1 -= u1[j];
                y0[j] = v0; y1[j] = v1;
                ys2[p] = make_float2(v0, a1 ? v1 : 0.0f);      // single STS.64
            }
        }
        __syncthreads();
    }

    // ---- sparsemax via Michelot (exact, no sort) ----
    {
        float s = 0.0f;
#pragma unroll
        for (int j = 0; j < NP; ++j) {
            int i0 = 2 * (t + j * TPB);
            bool a0 = (j == 0) || (i0 < n);
            bool a1 = (j == 0) || (i0 + 1 < n);
            if (a0) s += y0[j];
            if (a1) s += y1[j];
        }
#pragma unroll
        for (int d = 16; d; d >>= 1) s += __shfl_xor_sync(0xffffffffu, s, d);
        if (lane == 0) red_s[wid] = s;
        __syncthreads();
        if (t == 0) {
            float ss = 0.0f;
#pragma unroll
            for (int w = 0; w < NWARP; ++w) ss += red_s[w];
            s_tau = (ss - 1.0f) / (float)n;
            s_cnt = n;
        }
        __syncthreads();
    }

    float tau = s_tau;
    int prev_cnt = s_cnt;

    for (int itm = 0; itm < 64; ++itm) {
        float s = 0.0f;
        int   c = 0;
#pragma unroll
        for (int j = 0; j < NP; ++j) {
            int i0 = 2 * (t + j * TPB);
            bool a0 = (j == 0) || (i0 < n);
            bool a1 = (j == 0) || (i0 + 1 < n);
            if (a0 && y0[j] > tau) { s += y0[j]; ++c; }
            if (a1 && y1[j] > tau) { s += y1[j]; ++c; }
        }
#pragma unroll
        for (int d = 16; d; d >>= 1) {
            s += __shfl_xor_sync(0xffffffffu, s, d);
            c += __shfl_xor_sync(0xffffffffu, c, d);
        }
        if (lane == 0) { red_s[wid] = s; red_c[wid] = c; }
        __syncthreads();
        if (t == 0) {
            float ss = 0.0f; int cc = 0;
#pragma unroll
            for (int w = 0; w < NWARP; ++w) { ss += red_s[w]; cc += red_c[w]; }
            s_tau = (ss - 1.0f) / (float)cc;
            s_cnt = cc;
        }
        __syncthreads();
        tau = s_tau;
        int cnt_now = s_cnt;
        if (cnt_now == prev_cnt) break;
        prev_cnt = cnt_now;
    }

    float scale = (float)n;
#pragma unroll
    for (int j = 0; j < NP; ++j) {
        int i0 = 2 * (t + j * TPB);
        bool a0 = (j == 0) || (i0 < n);
        bool a1 = (j == 0) || (i0 + 1 < n);
        if (a0) out[off + i0]     = fmaxf(y0[j] - tau, 0.0f) * scale;
        if (a1) out[off + i0 + 1] = fmaxf(y1[j] - tau, 0.0f) * scale;
    }
}

// ---------------------------------------------------------------------------
extern "C" void kernel_launch(void* const* d_in, const int* in_sizes, int n_in,
                              void* d_out, int out_size) {
    const float* x     = (const float*)d_in[0];
    const int*   sizes = (const int*)  d_in[1];
    const int*   edges = (const int*)  d_in[2];
    float*       out   = (float*)d_out;
    int N = in_sizes[0];
    int B = in_sizes[1];

    pre_kernel<<<B, 512>>>(sizes, edges, N, B);
    main_kernel<<<B, TPB>>>(x, sizes, edges, out, N, B);
}